// round 11
// baseline (speedup 1.0000x reference)
#include <cuda_runtime.h>
#include <cuda_bf16.h>
#include <cstdint>
#include <math.h>

// ---------------------------------------------------------------------------
// Problem constants
// ---------------------------------------------------------------------------
#define BBATCH 16
#define DDIM   1024
#define TSEQ   1024
#define HDIM   1024
#define NCH    3072            // 3*H
#define MTOT   16384           // B*T
#define KPHYS  4096            // physical per-operand: [digit0 (2048) | digit1 (2048)]

// Quantization: v ~ S*(q0 + q1/254), 7-bit digits, range bound 6.5 sigma
#define QBOUND 6.5f
#define SIGW   0.02209708691f          // 1/sqrt(2048)
#define SA_    (QBOUND / 127.0f)
#define SB_    ((QBOUND * SIGW) / 127.0f)
#define INV254 0.0039370078740157f     // 1/254

// GEMM tiling: CTA 128x128, 16 warps of 32x32, k-iter = 128 int8 elements
#define TILE_M 128
#define TILE_N 128
#define NKITER 64              // 4 digit-product phases x 16 iters
#define NSTAGE 4

#define STAGE_BYTES  32768             // A 16KB + B 16KB
#define SM_A_OFF(s)  ((s) * STAGE_BYTES)
#define SM_B_OFF(s)  ((s) * STAGE_BYTES + 16384)
#define GEMM_SMEM    (NSTAGE * STAGE_BYTES)   // 131072

// ---------------------------------------------------------------------------
// Device scratch
// ---------------------------------------------------------------------------
__device__ int8_t g_Aq[(size_t)MTOT * KPHYS];             //  64 MB
__device__ int8_t g_Bq[(size_t)NCH  * KPHYS];             //  12 MB
__device__ float  g_gates[(size_t)MTOT * NCH];            // 192 MB (activated z|f|o)
__device__ float  g_state[(size_t)MTOT * 16 * 2];         // per-chunk (F, r)
__device__ float  g_cin[(size_t)MTOT * 16];               // per-chunk c_in

// ---------------------------------------------------------------------------
// PTX helpers (plain sm_80-level: valid on sm_103 without 'a' features)
// ---------------------------------------------------------------------------
__device__ __forceinline__ void cp_async16(uint32_t dst, const void* src) {
    asm volatile("cp.async.cg.shared.global [%0], [%1], 16;" :: "r"(dst), "l"(src));
}
__device__ __forceinline__ void cp_commit() {
    asm volatile("cp.async.commit_group;" ::: "memory");
}

__device__ __forceinline__ void ldsm_x4(uint32_t* r, uint32_t addr) {
    asm volatile("ldmatrix.sync.aligned.m8n8.x4.shared.b16 {%0,%1,%2,%3}, [%4];"
                 : "=r"(r[0]), "=r"(r[1]), "=r"(r[2]), "=r"(r[3]) : "r"(addr));
}

// s8 x s8 -> s32, m16n8k32 (exact integer accumulate)
__device__ __forceinline__ void mma_i8(int* d, const uint32_t* a,
                                       uint32_t b0, uint32_t b1) {
    asm volatile(
        "mma.sync.aligned.m16n8k32.row.col.s32.s8.s8.s32 "
        "{%0,%1,%2,%3}, {%4,%5,%6,%7}, {%8,%9}, {%0,%1,%2,%3};"
        : "+r"(d[0]), "+r"(d[1]), "+r"(d[2]), "+r"(d[3])
        : "r"(a[0]), "r"(a[1]), "r"(a[2]), "r"(a[3]), "r"(b0), "r"(b1));
}

// 2-digit quantization: v ~ S*(q0 + q1/254)
__device__ __forceinline__ void quant2(float v, float S, float invS,
                                       int8_t& q0, int8_t& q1) {
    int a = __float2int_rn(v * invS);
    a = max(-127, min(127, a));
    const float r = v - (float)a * S;
    int b = __float2int_rn(r * (254.0f * invS));
    b = max(-127, min(127, b));
    q0 = (int8_t)a;
    q1 = (int8_t)b;
}

// ---------------------------------------------------------------------------
// prep_A: transpose x [B,D,T] -> A int8 [m=(b,t)][k], phys [d0 | d1] segments,
//   within segment: k = tap*1024 + d; tap0 = x[t-1] (0 at t=0), tap1 = x[t]
// ---------------------------------------------------------------------------
__global__ __launch_bounds__(256)
void prep_A_kernel(const float* __restrict__ x) {
    __shared__ float tile[32][33];
    const int b  = blockIdx.z;
    const int t0 = blockIdx.x * 32;
    const int d0 = blockIdx.y * 32;
    const int tx = threadIdx.x;      // 0..31
    const int ty = threadIdx.y;      // 0..7

#pragma unroll
    for (int i = 0; i < 4; ++i) {
        const int dl = ty + i * 8;
        tile[dl][tx] = x[((size_t)b * DDIM + d0 + dl) * TSEQ + t0 + tx];
    }
    __syncthreads();

    const float SA = SA_, invSA = 1.0f / SA_;
#pragma unroll
    for (int i = 0; i < 4; ++i) {
        const int tl = ty + i * 8;
        const float v = tile[tx][tl];
        int8_t q0, q1;
        quant2(v, SA, invSA, q0, q1);
        const int t = t0 + tl;
        const int d = d0 + tx;
        const size_t m1 = (size_t)b * TSEQ + t;      // row using x[t] as tap1
        g_Aq[m1 * KPHYS + 1024 + d]        = q0;
        g_Aq[m1 * KPHYS + 2048 + 1024 + d] = q1;
        if (t + 1 < TSEQ) {                          // x[t] is tap0 of row t+1
            const size_t m0r = m1 + 1;
            g_Aq[m0r * KPHYS + d]        = q0;
            g_Aq[m0r * KPHYS + 2048 + d] = q1;
        }
        if (t == 0) {                                // causal pad: tap0 @ t=0
            g_Aq[m1 * KPHYS + d]        = 0;
            g_Aq[m1 * KPHYS + 2048 + d] = 0;
        }
    }
}

// ---------------------------------------------------------------------------
// prep_B: w [3H, D, 2] -> B int8 [n][k], phys [e0 | e1]
// ---------------------------------------------------------------------------
__global__ __launch_bounds__(512)
void prep_B_kernel(const float* __restrict__ w) {
    const int idx = blockIdx.x * 512 + threadIdx.x;   // over 3072*1024
    const int n = idx >> 10;
    const int d = idx & 1023;
    const float2 wv = *(const float2*)&w[(size_t)idx * 2];   // w[n][d][0..1]
    const float SB = SB_, invSB = 1.0f / SB_;
#pragma unroll
    for (int tap = 0; tap < 2; ++tap) {
        const float v = tap ? wv.y : wv.x;
        int8_t q0, q1;
        quant2(v, SB, invSB, q0, q1);
        const size_t base = (size_t)n * KPHYS + tap * 1024 + d;
        g_Bq[base]        = q0;
        g_Bq[base + 2048] = q1;
    }
}

// ---------------------------------------------------------------------------
// GEMM: gates = act( Sa*Sb*(P00 + (P01+P10)/254 + P11/254^2) + bias )
// Phases (low weight first, folded): kt 0-15: d1*e1; 16-31: d0*e1;
// 32-47: d1*e0; 48-63: d0*e0.  Fold after kt 15, 47, and end:
//   facc = facc/254 + (float)iacc ; iacc = 0
// smem tiles: K-major 128B rows, SW128 xor swizzle (same geometry as the
// validated bf16 version: k32-int8 bytes == k16-bf16 bytes).
// ---------------------------------------------------------------------------
__device__ __forceinline__ void fill_stage(int kt, int s, int tid,
                                           uint32_t smem_base, int m0, int n0) {
    int aoff, boff;                                   // physical byte offsets
    if (kt < 16)      { aoff = 2048 + kt * 128;        boff = 2048 + kt * 128; }
    else if (kt < 32) { aoff = (kt - 16) * 128;        boff = 2048 + (kt - 16) * 128; }
    else if (kt < 48) { aoff = 2048 + (kt - 32) * 128; boff = (kt - 32) * 128; }
    else              { aoff = (kt - 48) * 128;        boff = (kt - 48) * 128; }
    const char* Ab = (const char*)g_Aq;
    const char* Bb = (const char*)g_Bq;
#pragma unroll
    for (int i = 0; i < 2; ++i) {                    // A: 1024 x 16B chunks
        const int c   = tid + i * 512;
        const int row = c >> 3;
        const int cb  = (c & 7) << 4;
        const uint32_t off = (row << 7) + cb;
        const uint32_t sw  = off ^ ((off >> 3) & 0x70);
        cp_async16(smem_base + SM_A_OFF(s) + sw,
                   Ab + (size_t)(m0 + row) * KPHYS + aoff + cb);
    }
#pragma unroll
    for (int i = 0; i < 2; ++i) {                    // B: 1024 x 16B chunks
        const int c   = tid + i * 512;
        const int row = c >> 3;
        const int cb  = (c & 7) << 4;
        const uint32_t off = (row << 7) + cb;
        const uint32_t sw  = off ^ ((off >> 3) & 0x70);
        cp_async16(smem_base + SM_B_OFF(s) + sw,
                   Bb + (size_t)(n0 + row) * KPHYS + boff + cb);
    }
    cp_commit();
}

__global__ __launch_bounds__(512, 1)
void qrnn_gemm_i8(const float* __restrict__ bias) {
    extern __shared__ __align__(1024) char smem[];
    const uint32_t smem_base = (uint32_t)__cvta_generic_to_shared(smem);
    const int tid = threadIdx.x;
    const int wid = tid >> 5;
    const int l   = tid & 31;
    const int n0 = blockIdx.x * TILE_N;   // n fastest: A m-panel + B L2 reuse
    const int m0 = blockIdx.y * TILE_M;

    const int warp_m = wid & 3;           // 4 warps over M (32 rows each)
    const int warp_n = wid >> 2;          // 4 warps over N (32 cols each)

    // ldmatrix lane geometry (byte-identical to validated bf16 version)
    const int csel   = (l >> 4) & 1;
    const uint32_t xorv = (uint32_t)(l & 7) << 4;    // SW128 xor term
    uint32_t kcx[4];
#pragma unroll
    for (int ks = 0; ks < 4; ++ks)
        kcx[ks] = ((uint32_t)(ks * 32 + 16 * csel)) ^ xorv;

    const uint32_t aRow = (uint32_t)(warp_m * 32 + (l & 15)) << 7;
    const uint32_t bRow = (uint32_t)(warp_n * 32 + (l & 15)) << 7;

    int   iacc[2][4][4];
    float facc[2][4][4];
#pragma unroll
    for (int mt = 0; mt < 2; ++mt)
#pragma unroll
        for (int nt = 0; nt < 4; ++nt)
#pragma unroll
            for (int q = 0; q < 4; ++q) { iacc[mt][nt][q] = 0; facc[mt][nt][q] = 0.f; }

    fill_stage(0, 0, tid, smem_base, m0, n0);
    fill_stage(1, 1, tid, smem_base, m0, n0);
    fill_stage(2, 2, tid, smem_base, m0, n0);

    for (int kt = 0; kt < NKITER; ++kt) {
        const int s = kt & 3;
        if (kt < NKITER - 2) {
            asm volatile("cp.async.wait_group 2;" ::: "memory");
        } else if (kt == NKITER - 2) {
            asm volatile("cp.async.wait_group 1;" ::: "memory");
        } else {
            asm volatile("cp.async.wait_group 0;" ::: "memory");
        }
        __syncthreads();

        const uint32_t aBase = smem_base + SM_A_OFF(s) + aRow;
        const uint32_t bBase = smem_base + SM_B_OFF(s) + bRow;

#pragma unroll
        for (int ks = 0; ks < 4; ++ks) {             // each ks = k32 int8
            uint32_t a[2][4], bf[2][4];
#pragma unroll
            for (int mt = 0; mt < 2; ++mt)
                ldsm_x4(a[mt], aBase + mt * 2048 + kcx[ks]);
#pragma unroll
            for (int ng = 0; ng < 2; ++ng)
                ldsm_x4(bf[ng], bBase + ng * 2048 + kcx[ks]);
#pragma unroll
            for (int mt = 0; mt < 2; ++mt) {
#pragma unroll
                for (int ng = 0; ng < 2; ++ng) {
                    mma_i8(iacc[mt][2 * ng],     a[mt], bf[ng][0], bf[ng][2]);
                    mma_i8(iacc[mt][2 * ng + 1], a[mt], bf[ng][1], bf[ng][3]);
                }
            }
        }

        if (kt == 15 || kt == 47) {                  // fold phase into float acc
#pragma unroll
            for (int mt = 0; mt < 2; ++mt)
#pragma unroll
                for (int nt = 0; nt < 4; ++nt)
#pragma unroll
                    for (int q = 0; q < 4; ++q) {
                        facc[mt][nt][q] = facc[mt][nt][q] * INV254 + (float)iacc[mt][nt][q];
                        iacc[mt][nt][q] = 0;
                    }
        }

        if (kt + 3 < NKITER)
            fill_stage(kt + 3, (kt + 3) & 3, tid, smem_base, m0, n0);
    }

    // final fold: facc = P00 + (P01+P10)/254 + P11/254^2
#pragma unroll
    for (int mt = 0; mt < 2; ++mt)
#pragma unroll
        for (int nt = 0; nt < 4; ++nt)
#pragma unroll
            for (int q = 0; q < 4; ++q)
                facc[mt][nt][q] = facc[mt][nt][q] * INV254 + (float)iacc[mt][nt][q];

    // ---- epilogue: scale + bias + activation -> g_gates ----
    const float OUTSCALE = SA_ * SB_;
    const int region = n0 >> 10;                 // 0=z(tanh), 1/2=sigmoid
    const int mW = m0 + warp_m * 32;
    const int nW = n0 + warp_n * 32;
#pragma unroll
    for (int mt = 0; mt < 2; ++mt) {
#pragma unroll
        for (int nt = 0; nt < 4; ++nt) {
            const int col  = nW + nt * 8 + 2 * (l & 3);
            const float b0 = bias[col];
            const float b1 = bias[col + 1];
#pragma unroll
            for (int half = 0; half < 2; ++half) {
                const int row = mW + mt * 16 + (l >> 2) + 8 * half;
                float gx = facc[mt][nt][2 * half]     * OUTSCALE + b0;
                float gy = facc[mt][nt][2 * half + 1] * OUTSCALE + b1;
                float vx, vy;
                if (region == 0) {
                    vx = 2.f / (1.f + __expf(-2.f * gx)) - 1.f;
                    vy = 2.f / (1.f + __expf(-2.f * gy)) - 1.f;
                } else {
                    vx = 1.f / (1.f + __expf(-gx));
                    vy = 1.f / (1.f + __expf(-gy));
                }
                *(float2*)&g_gates[(size_t)row * NCH + col] = make_float2(vx, vy);
            }
        }
    }
}

// ---------------------------------------------------------------------------
// Chunked fo-pooling scan: c_t = f*(c_{t-1} - z) + z ;  h_t = o*c_t
// 16 chunks of 64 per (b,h) chain -> 262K threads.
// ---------------------------------------------------------------------------
__global__ __launch_bounds__(256)
void qrnn_scan_pass1() {
    const int idx   = blockIdx.x * 256 + threadIdx.x;   // 0..262143
    const int b     = idx >> 14;
    const int chunk = (idx >> 10) & 15;
    const int h     = idx & 1023;
    const float* __restrict__ g =
        g_gates + ((size_t)(b * TSEQ + chunk * 64)) * NCH + h;
    float c = 0.f, F = 1.f;
#pragma unroll 4
    for (int t = 0; t < 64; ++t) {
        const float z = g[(size_t)t * NCH];
        const float f = g[(size_t)t * NCH + HDIM];
        c = f * (c - z) + z;
        F *= f;
    }
    const size_t st = ((size_t)(b * 1024 + h) * 16 + chunk) * 2;
    g_state[st]     = F;
    g_state[st + 1] = c;
}

__global__ __launch_bounds__(256)
void qrnn_scan_combine() {
    const int chain = blockIdx.x * 256 + threadIdx.x;   // 0..16383
    const float* st = g_state + (size_t)chain * 32;
    float* ci = g_cin + (size_t)chain * 16;
    float c = 0.f;
#pragma unroll
    for (int ch = 0; ch < 16; ++ch) {
        ci[ch] = c;
        c = st[ch * 2] * c + st[ch * 2 + 1];
    }
}

__global__ __launch_bounds__(256)
void qrnn_scan_pass2(float* __restrict__ out) {
    const int idx   = blockIdx.x * 256 + threadIdx.x;
    const int b     = idx >> 14;
    const int chunk = (idx >> 10) & 15;
    const int h     = idx & 1023;
    const float* __restrict__ g =
        g_gates + ((size_t)(b * TSEQ + chunk * 64)) * NCH + h;
    float* __restrict__ cout = out + ((size_t)b * TSEQ + chunk * 64) * HDIM + h;
    float* __restrict__ hout = cout + (size_t)BBATCH * TSEQ * HDIM;

    float c = g_cin[(size_t)(b * 1024 + h) * 16 + chunk];
#pragma unroll 4
    for (int t = 0; t < 64; ++t) {
        const float z = g[(size_t)t * NCH];
        const float f = g[(size_t)t * NCH + HDIM];
        const float o = g[(size_t)t * NCH + 2 * HDIM];
        c = f * (c - z) + z;
        cout[(size_t)t * HDIM] = c;
        hout[(size_t)t * HDIM] = o * c;
    }
}

// ---------------------------------------------------------------------------
extern "C" void kernel_launch(void* const* d_in, const int* in_sizes, int n_in,
                              void* d_out, int out_size)
{
    const float* x    = (const float*)d_in[0];   // [B, D, T]
    const float* w    = (const float*)d_in[1];   // [3H, D, 2]
    const float* bias = (const float*)d_in[2];   // [3H]
    float* out = (float*)d_out;

    cudaFuncSetAttribute(qrnn_gemm_i8, cudaFuncAttributeMaxDynamicSharedMemorySize,
                         GEMM_SMEM);

    prep_A_kernel<<<dim3(TSEQ / 32, DDIM / 32, BBATCH), dim3(32, 8)>>>(x);
    prep_B_kernel<<<(NCH * DDIM) / 512, 512>>>(w);

    qrnn_gemm_i8<<<dim3(NCH / TILE_N, MTOT / TILE_M), 512, GEMM_SMEM>>>(bias);

    qrnn_scan_pass1<<<(MTOT * 16) / 256, 256>>>();
    qrnn_scan_combine<<<MTOT / 256, 256>>>();
    qrnn_scan_pass2<<<(MTOT * 16) / 256, 256>>>(out);
}

// round 14
// speedup vs baseline: 2.9297x; 2.9297x over previous
#include <cuda_runtime.h>
#include <cuda_bf16.h>
#include <cstdint>
#include <math.h>

// ---------------------------------------------------------------------------
// Problem constants
// ---------------------------------------------------------------------------
#define BBATCH 16
#define DDIM   1024
#define TSEQ   1024
#define HDIM   1024
#define NCH    3072            // 3*H
#define MTOT   16384           // B*T
#define KCAT   6144            // logical K: 3 segs [Ahi|Ahi|Alo] x [Bhi|Blo|Bhi]
#define KA     4096            // physical A: [Ahi|Alo]
#define KB     4096            // physical B: [Bhi|Blo]

// GEMM tiling: CTA 256x128, 8 warps of 64x64, full operand double-buffering
#define TILE_M 256
#define TILE_N 128
#define BKK    64
#define NKITER (KCAT / BKK)    // 96 logical k-tiles
#define NSTAGE 3

#define STAGE_BYTES  49152             // A 32KB + B 16KB
#define SM_A_OFF(s)  ((s) * STAGE_BYTES)
#define SM_B_OFF(s)  ((s) * STAGE_BYTES + 32768)
#define GEMM_SMEM    (NSTAGE * STAGE_BYTES)   // 147456

// ---------------------------------------------------------------------------
// Device scratch
// ---------------------------------------------------------------------------
__device__ __nv_bfloat16 g_A[(size_t)MTOT * KA];          // 128 MB
__device__ __nv_bfloat16 g_B[(size_t)NCH  * KB];          //  24 MB
__device__ float         g_gates[(size_t)MTOT * NCH];     // 192 MB (activated z|f|o)
__device__ float         g_state[(size_t)MTOT * 16 * 2];  // per-chunk (F, r)
__device__ float         g_cin[(size_t)MTOT * 16];        // per-chunk c_in

// ---------------------------------------------------------------------------
// PTX helpers (plain sm_80-level: valid on sm_103 without 'a' features)
// ---------------------------------------------------------------------------
__device__ __forceinline__ void cp_async16(uint32_t dst, const void* src) {
    asm volatile("cp.async.cg.shared.global [%0], [%1], 16;" :: "r"(dst), "l"(src));
}
__device__ __forceinline__ void cp_commit() {
    asm volatile("cp.async.commit_group;" ::: "memory");
}

__device__ __forceinline__ void ldsm_x4(uint32_t* r, uint32_t addr) {
    asm volatile("ldmatrix.sync.aligned.m8n8.x4.shared.b16 {%0,%1,%2,%3}, [%4];"
                 : "=r"(r[0]), "=r"(r[1]), "=r"(r[2]), "=r"(r[3]) : "r"(addr));
}

__device__ __forceinline__ void mma16816(float* d, const uint32_t* a,
                                         uint32_t b0, uint32_t b1) {
    asm volatile(
        "mma.sync.aligned.m16n8k16.row.col.f32.bf16.bf16.f32 "
        "{%0,%1,%2,%3}, {%4,%5,%6,%7}, {%8,%9}, {%0,%1,%2,%3};"
        : "+f"(d[0]), "+f"(d[1]), "+f"(d[2]), "+f"(d[3])
        : "r"(a[0]), "r"(a[1]), "r"(a[2]), "r"(a[3]), "r"(b0), "r"(b1));
}

// ---------------------------------------------------------------------------
// prep_A: transpose x [B,D,T] -> A bf16 [m=(b,t)][k], physical [Ahi|Alo]
//   k = seg*2048 + tap*1024 + d; tap0 = x[t-1] (0 at t=0), tap1 = x[t]
// ---------------------------------------------------------------------------
__global__ __launch_bounds__(256)
void prep_A_kernel(const float* __restrict__ x) {
    __shared__ float tile[32][33];
    const int b  = blockIdx.z;
    const int t0 = blockIdx.x * 32;
    const int d0 = blockIdx.y * 32;
    const int tx = threadIdx.x;      // 0..31
    const int ty = threadIdx.y;      // 0..7

#pragma unroll
    for (int i = 0; i < 4; ++i) {
        const int dl = ty + i * 8;
        tile[dl][tx] = x[((size_t)b * DDIM + d0 + dl) * TSEQ + t0 + tx];
    }
    __syncthreads();

#pragma unroll
    for (int i = 0; i < 4; ++i) {
        const int tl = ty + i * 8;
        const float v = tile[tx][tl];
        const __nv_bfloat16 hi = __float2bfloat16(v);
        const __nv_bfloat16 lo = __float2bfloat16(v - __bfloat162float(hi));
        const int t = t0 + tl;
        const int d = d0 + tx;
        const size_t m1 = (size_t)b * TSEQ + t;      // row using x[t] as tap1
        g_A[m1 * KA + 1024 + d]        = hi;
        g_A[m1 * KA + 2048 + 1024 + d] = lo;
        if (t + 1 < TSEQ) {                          // x[t] is tap0 of row t+1
            const size_t m0r = m1 + 1;
            g_A[m0r * KA + d]        = hi;
            g_A[m0r * KA + 2048 + d] = lo;
        }
        if (t == 0) {                                // causal pad: tap0 @ t=0
            const __nv_bfloat16 z = __float2bfloat16(0.f);
            g_A[m1 * KA + d]        = z;
            g_A[m1 * KA + 2048 + d] = z;
        }
    }
}

// ---------------------------------------------------------------------------
// prep_B: w [3H, D, 2] -> B bf16 [n][k], physical [Bhi|Blo]
// ---------------------------------------------------------------------------
__global__ __launch_bounds__(512)
void prep_B_kernel(const float* __restrict__ w) {
    const int idx = blockIdx.x * 512 + threadIdx.x;   // over 3072*1024
    const int n = idx >> 10;
    const int d = idx & 1023;
    const float2 wv = *(const float2*)&w[(size_t)idx * 2];   // w[n][d][0..1]
#pragma unroll
    for (int tap = 0; tap < 2; ++tap) {
        const float v = tap ? wv.y : wv.x;
        const __nv_bfloat16 hi = __float2bfloat16(v);
        const __nv_bfloat16 lo = __float2bfloat16(v - __bfloat162float(hi));
        const size_t base = (size_t)n * KB + tap * 1024 + d;
        g_B[base]        = hi;
        g_B[base + 2048] = lo;
    }
}

// ---------------------------------------------------------------------------
// GEMM: g_gates = act( A_cat @ B_cat^T + bias ), logical K = 6144 over
// physical dedup'd A/B. CTA 256x128, 256 threads (8 warps, 64x64 warp
// tiles), BK=64, 3-stage cp.async pipeline, bf16 mma.sync with FULL
// operand double-buffering (ldsm for ks+1 overlaps mma for ks).
// smem tiles: K-major 128B rows, SW128 xor swizzle.
// ---------------------------------------------------------------------------
__device__ __forceinline__ void fill_stage(int kt, int s, int tid,
                                           uint32_t smem_base, int m0, int n0) {
    // logical k-tile -> physical k offset (dedup'd hi segment)
    const int akt = (kt < 32) ? kt : kt - 32;   // [Ahi|Ahi|Alo] -> [Ahi|Alo]
    const int bkt = (kt < 64) ? kt : kt - 64;   // [Bhi|Blo|Bhi] -> [Bhi|Blo]
    const char* Abase = (const char*)g_A;
    const char* Bbase = (const char*)g_B;
#pragma unroll
    for (int i = 0; i < 8; ++i) {                    // A: 2048 x 16B
        const int c   = tid + i * 256;
        const int row = c >> 3;
        const int cb  = (c & 7) << 4;
        const uint32_t off = (row << 7) + cb;
        const uint32_t sw  = off ^ ((off >> 3) & 0x70);
        cp_async16(smem_base + SM_A_OFF(s) + sw,
                   Abase + ((size_t)(m0 + row) * KA + akt * 64) * 2 + cb);
    }
#pragma unroll
    for (int i = 0; i < 4; ++i) {                    // B: 1024 x 16B
        const int c   = tid + i * 256;
        const int row = c >> 3;
        const int cb  = (c & 7) << 4;
        const uint32_t off = (row << 7) + cb;
        const uint32_t sw  = off ^ ((off >> 3) & 0x70);
        cp_async16(smem_base + SM_B_OFF(s) + sw,
                   Bbase + ((size_t)(n0 + row) * KB + bkt * 64) * 2 + cb);
    }
    cp_commit();
}

__global__ __launch_bounds__(256, 1)
void qrnn_gemm_tc(const float* __restrict__ bias) {
    extern __shared__ __align__(1024) char smem[];
    const uint32_t smem_base = (uint32_t)__cvta_generic_to_shared(smem);
    const int tid = threadIdx.x;
    const int wid = tid >> 5;
    const int l   = tid & 31;
    const int n0 = blockIdx.x * TILE_N;   // n fastest: A m-panel + B L2 reuse
    const int m0 = blockIdx.y * TILE_M;

    const int warp_m = wid & 3;           // 4 warps over M (64 rows each)
    const int warp_n = wid >> 2;          // 2 warps over N (64 cols each)

    // ldmatrix lane geometry:
    //   r=l&7 row-within-8, (l>>3)&1 -> +8 row, (l>>4)&1 -> +16B col
    const int r      = l & 7;
    const int rsel   = (l >> 3) & 1;
    const int csel   = (l >> 4) & 1;
    const uint32_t xorv = (uint32_t)r << 4;          // SW128 xor term
    uint32_t kcx[4];
#pragma unroll
    for (int ks = 0; ks < 4; ++ks)
        kcx[ks] = ((uint32_t)(ks * 32 + 16 * csel)) ^ xorv;

    const uint32_t aRow = (uint32_t)(warp_m * 64 + r + 8 * rsel) << 7;
    const uint32_t bRow = (uint32_t)(warp_n * 64 + r + 8 * rsel) << 7;

    float acc[4][8][4];
#pragma unroll
    for (int mt = 0; mt < 4; ++mt)
#pragma unroll
        for (int nt = 0; nt < 8; ++nt)
#pragma unroll
            for (int q = 0; q < 4; ++q) acc[mt][nt][q] = 0.f;

    fill_stage(0, 0, tid, smem_base, m0, n0);
    fill_stage(1, 1, tid, smem_base, m0, n0);

    // double-buffered operand registers
    uint32_t a2[2][4][4], b2[2][4][4];

    for (int kt = 0; kt < NKITER; ++kt) {
        const int s = kt % NSTAGE;
        if (kt + 2 < NKITER) {
            asm volatile("cp.async.wait_group 1;" ::: "memory");
        } else {
            asm volatile("cp.async.wait_group 0;" ::: "memory");
        }
        __syncthreads();

        const uint32_t aBase = smem_base + SM_A_OFF(s) + aRow;
        const uint32_t bBase = smem_base + SM_B_OFF(s) + bRow;

        // cold load ks=0 (interleaved B/A so earliest consumers issue first)
#pragma unroll
        for (int g = 0; g < 4; ++g) {
            ldsm_x4(b2[0][g], bBase + g * 2048 + kcx[0]);
            ldsm_x4(a2[0][g], aBase + g * 2048 + kcx[0]);
        }

        // issue next stage's fills now (async; overlaps with mma below).
        // Target stage (kt+2)%3 == stage read at kt-1: safe post-sync.
        if (kt + 2 < NKITER)
            fill_stage(kt + 2, (kt + 2) % NSTAGE, tid, smem_base, m0, n0);

#pragma unroll
        for (int ks = 0; ks < 4; ++ks) {
            const int cur = ks & 1;
            const int nxt = cur ^ 1;
            if (ks < 3) {                            // prefetch ks+1 operands
#pragma unroll
                for (int g = 0; g < 4; ++g) {
                    ldsm_x4(b2[nxt][g], bBase + g * 2048 + kcx[ks + 1]);
                    ldsm_x4(a2[nxt][g], aBase + g * 2048 + kcx[ks + 1]);
                }
            }
#pragma unroll
            for (int mt = 0; mt < 4; ++mt) {
#pragma unroll
                for (int ng = 0; ng < 4; ++ng) {
                    mma16816(acc[mt][2 * ng],     a2[cur][mt], b2[cur][ng][0], b2[cur][ng][2]);
                    mma16816(acc[mt][2 * ng + 1], a2[cur][mt], b2[cur][ng][1], b2[cur][ng][3]);
                }
            }
        }
    }

    // ---- epilogue: bias + activation -> g_gates ----
    const int region = n0 >> 10;                 // 0=z(tanh), 1/2=sigmoid
    const int mW = m0 + warp_m * 64;
    const int nW = n0 + warp_n * 64;
#pragma unroll
    for (int mt = 0; mt < 4; ++mt) {
#pragma unroll
        for (int nt = 0; nt < 8; ++nt) {
            const int col  = nW + nt * 8 + 2 * (l & 3);
            const float b0 = bias[col];
            const float b1 = bias[col + 1];
#pragma unroll
            for (int half = 0; half < 2; ++half) {
                const int row = mW + mt * 16 + (l >> 2) + 8 * half;
                float gx = acc[mt][nt][2 * half]     + b0;
                float gy = acc[mt][nt][2 * half + 1] + b1;
                float vx, vy;
                if (region == 0) {
                    vx = 2.f / (1.f + __expf(-2.f * gx)) - 1.f;
                    vy = 2.f / (1.f + __expf(-2.f * gy)) - 1.f;
                } else {
                    vx = 1.f / (1.f + __expf(-gx));
                    vy = 1.f / (1.f + __expf(-gy));
                }
                *(float2*)&g_gates[(size_t)row * NCH + col] = make_float2(vx, vy);
            }
        }
    }
}

// ---------------------------------------------------------------------------
// Chunked fo-pooling scan: c_t = f*(c_{t-1} - z) + z ;  h_t = o*c_t
// 16 chunks of 64 per (b,h) chain -> 262K threads.
// ---------------------------------------------------------------------------
__global__ __launch_bounds__(256)
void qrnn_scan_pass1() {
    const int idx   = blockIdx.x * 256 + threadIdx.x;   // 0..262143
    const int b     = idx >> 14;
    const int chunk = (idx >> 10) & 15;
    const int h     = idx & 1023;
    const float* __restrict__ g =
        g_gates + ((size_t)(b * TSEQ + chunk * 64)) * NCH + h;
    float c = 0.f, F = 1.f;
#pragma unroll 4
    for (int t = 0; t < 64; ++t) {
        const float z = g[(size_t)t * NCH];
        const float f = g[(size_t)t * NCH + HDIM];
        c = f * (c - z) + z;
        F *= f;
    }
    const size_t st = ((size_t)(b * 1024 + h) * 16 + chunk) * 2;
    g_state[st]     = F;
    g_state[st + 1] = c;
}

__global__ __launch_bounds__(256)
void qrnn_scan_combine() {
    const int chain = blockIdx.x * 256 + threadIdx.x;   // 0..16383
    const float* st = g_state + (size_t)chain * 32;
    float* ci = g_cin + (size_t)chain * 16;
    float c = 0.f;
#pragma unroll
    for (int ch = 0; ch < 16; ++ch) {
        ci[ch] = c;
        c = st[ch * 2] * c + st[ch * 2 + 1];
    }
}

__global__ __launch_bounds__(256)
void qrnn_scan_pass2(float* __restrict__ out) {
    const int idx   = blockIdx.x * 256 + threadIdx.x;
    const int b     = idx >> 14;
    const int chunk = (idx >> 10) & 15;
    const int h     = idx & 1023;
    const float* __restrict__ g =
        g_gates + ((size_t)(b * TSEQ + chunk * 64)) * NCH + h;
    float* __restrict__ cout = out + ((size_t)b * TSEQ + chunk * 64) * HDIM + h;
    float* __restrict__ hout = cout + (size_t)BBATCH * TSEQ * HDIM;

    float c = g_cin[(size_t)(b * 1024 + h) * 16 + chunk];
#pragma unroll 4
    for (int t = 0; t < 64; ++t) {
        const float z = __ldcs(&g[(size_t)t * NCH]);
        const float f = __ldcs(&g[(size_t)t * NCH + HDIM]);
        const float o = __ldcs(&g[(size_t)t * NCH + 2 * HDIM]);
        c = f * (c - z) + z;
        __stcs(&cout[(size_t)t * HDIM], c);          // final outputs: never re-read
        __stcs(&hout[(size_t)t * HDIM], o * c);
    }
}

// ---------------------------------------------------------------------------
extern "C" void kernel_launch(void* const* d_in, const int* in_sizes, int n_in,
                              void* d_out, int out_size)
{
    const float* x    = (const float*)d_in[0];   // [B, D, T]
    const float* w    = (const float*)d_in[1];   // [3H, D, 2]
    const float* bias = (const float*)d_in[2];   // [3H]
    float* out = (float*)d_out;

    cudaFuncSetAttribute(qrnn_gemm_tc, cudaFuncAttributeMaxDynamicSharedMemorySize,
                         GEMM_SMEM);

    prep_A_kernel<<<dim3(TSEQ / 32, DDIM / 32, BBATCH), dim3(32, 8)>>>(x);
    prep_B_kernel<<<(NCH * DDIM) / 512, 512>>>(w);

    qrnn_gemm_tc<<<dim3(NCH / TILE_N, MTOT / TILE_M), 256, GEMM_SMEM>>>(bias);

    qrnn_scan_pass1<<<(MTOT * 16) / 256, 256>>>();
    qrnn_scan_combine<<<MTOT / 256, 256>>>();
    qrnn_scan_pass2<<<(MTOT * 16) / 256, 256>>>(out);
}

// round 16
// speedup vs baseline: 7.8609x; 2.6832x over previous
#include <cuda_runtime.h>
#include <cuda_fp16.h>
#include <cstdint>
#include <math.h>

// ---------------------------------------------------------------------------
// Problem constants
// ---------------------------------------------------------------------------
#define BBATCH 16
#define DDIM   1024
#define TSEQ   1024
#define HDIM   1024
#define NCH    3072            // 3*H
#define MTOT   16384           // B*T
#define KTOT   2048            // K = 2 taps x 1024 channels, single fp16 pass

// GEMM tiling: CTA 256x128, 16 warps of 64x32, 4-stage cp.async (R9 config)
#define TILE_M 256
#define TILE_N 128
#define BKK    64
#define NKITER (KTOT / BKK)    // 32 k-tiles
#define NSTAGE 4

#define STAGE_BYTES  49152             // A 32KB + B 16KB
#define SM_A_OFF(s)  ((s) * STAGE_BYTES)
#define SM_B_OFF(s)  ((s) * STAGE_BYTES + 32768)
#define GEMM_SMEM    (NSTAGE * STAGE_BYTES)   // 196608

// ---------------------------------------------------------------------------
// Device scratch
// ---------------------------------------------------------------------------
__device__ __half g_A[(size_t)MTOT * KTOT];               //  64 MB
__device__ __half g_B[(size_t)NCH  * KTOT];               //  12 MB
__device__ float  g_gates[(size_t)MTOT * NCH];            // 192 MB (activated z|f|o)
__device__ float  g_state[(size_t)MTOT * 16 * 2];         // per-chunk (F, r)
__device__ float  g_cin[(size_t)MTOT * 16];               // per-chunk c_in

// ---------------------------------------------------------------------------
// PTX helpers (plain sm_80-level: valid on sm_103 without 'a' features)
// ---------------------------------------------------------------------------
__device__ __forceinline__ void cp_async16(uint32_t dst, const void* src) {
    asm volatile("cp.async.cg.shared.global [%0], [%1], 16;" :: "r"(dst), "l"(src));
}
__device__ __forceinline__ void cp_commit() {
    asm volatile("cp.async.commit_group;" ::: "memory");
}

__device__ __forceinline__ void ldsm_x4(uint32_t* r, uint32_t addr) {
    asm volatile("ldmatrix.sync.aligned.m8n8.x4.shared.b16 {%0,%1,%2,%3}, [%4];"
                 : "=r"(r[0]), "=r"(r[1]), "=r"(r[2]), "=r"(r[3]) : "r"(addr));
}

__device__ __forceinline__ void mma16816(float* d, const uint32_t* a,
                                         uint32_t b0, uint32_t b1) {
    asm volatile(
        "mma.sync.aligned.m16n8k16.row.col.f32.f16.f16.f32 "
        "{%0,%1,%2,%3}, {%4,%5,%6,%7}, {%8,%9}, {%0,%1,%2,%3};"
        : "+f"(d[0]), "+f"(d[1]), "+f"(d[2]), "+f"(d[3])
        : "r"(a[0]), "r"(a[1]), "r"(a[2]), "r"(a[3]), "r"(b0), "r"(b1));
}

// ---------------------------------------------------------------------------
// prep_A: transpose x [B,D,T] -> A fp16 [m=(b,t)][k], k = tap*1024 + d
//   tap0 = x[t-1] (0 at t=0), tap1 = x[t]
// ---------------------------------------------------------------------------
__global__ __launch_bounds__(256)
void prep_A_kernel(const float* __restrict__ x) {
    __shared__ float tile[32][33];
    const int b  = blockIdx.z;
    const int t0 = blockIdx.x * 32;
    const int d0 = blockIdx.y * 32;
    const int tx = threadIdx.x;      // 0..31
    const int ty = threadIdx.y;      // 0..7

#pragma unroll
    for (int i = 0; i < 4; ++i) {
        const int dl = ty + i * 8;
        tile[dl][tx] = x[((size_t)b * DDIM + d0 + dl) * TSEQ + t0 + tx];
    }
    __syncthreads();

#pragma unroll
    for (int i = 0; i < 4; ++i) {
        const int tl = ty + i * 8;
        const __half hv = __float2half_rn(tile[tx][tl]);
        const int t = t0 + tl;
        const int d = d0 + tx;
        const size_t m1 = (size_t)b * TSEQ + t;      // row using x[t] as tap1
        g_A[m1 * KTOT + 1024 + d] = hv;
        if (t + 1 < TSEQ)                            // x[t] is tap0 of row t+1
            g_A[(m1 + 1) * KTOT + d] = hv;
        if (t == 0)                                  // causal pad: tap0 @ t=0
            g_A[m1 * KTOT + d] = __float2half_rn(0.f);
    }
}

// ---------------------------------------------------------------------------
// prep_B: w [3H, D, 2] -> B fp16 [n][k], k = tap*1024 + d
// ---------------------------------------------------------------------------
__global__ __launch_bounds__(512)
void prep_B_kernel(const float* __restrict__ w) {
    const int idx = blockIdx.x * 512 + threadIdx.x;   // over 3072*1024
    const int n = idx >> 10;
    const int d = idx & 1023;
    const float2 wv = *(const float2*)&w[(size_t)idx * 2];   // w[n][d][0..1]
    g_B[(size_t)n * KTOT + d]        = __float2half_rn(wv.x);
    g_B[(size_t)n * KTOT + 1024 + d] = __float2half_rn(wv.y);
}

// ---------------------------------------------------------------------------
// GEMM: g_gates = act( A @ B^T + bias ), K = 2048, single fp16 pass.
// CTA 256x128, 512 threads (16 warps, 64x32 warp tiles), BK=64, 4-stage
// cp.async pipeline, fp16 mma.sync (fp32 accumulate).
// smem tiles: K-major 128B rows with SW128 xor swizzle (ldmatrix-friendly).
// ---------------------------------------------------------------------------
__device__ __forceinline__ void fill_stage(int kt, int s, int tid,
                                           uint32_t smem_base, int m0, int n0) {
    const char* Abase = (const char*)g_A;
    const char* Bbase = (const char*)g_B;
#pragma unroll
    for (int i = 0; i < 4; ++i) {                    // A: 2048 x 16B
        const int c   = tid + i * 512;
        const int row = c >> 3;
        const int cb  = (c & 7) << 4;
        const uint32_t off = (row << 7) + cb;
        const uint32_t sw  = off ^ ((off >> 3) & 0x70);
        cp_async16(smem_base + SM_A_OFF(s) + sw,
                   Abase + ((size_t)(m0 + row) * KTOT + kt * 64) * 2 + cb);
    }
#pragma unroll
    for (int i = 0; i < 2; ++i) {                    // B: 1024 x 16B
        const int c   = tid + i * 512;
        const int row = c >> 3;
        const int cb  = (c & 7) << 4;
        const uint32_t off = (row << 7) + cb;
        const uint32_t sw  = off ^ ((off >> 3) & 0x70);
        cp_async16(smem_base + SM_B_OFF(s) + sw,
                   Bbase + ((size_t)(n0 + row) * KTOT + kt * 64) * 2 + cb);
    }
    cp_commit();
}

__global__ __launch_bounds__(512, 1)
void qrnn_gemm_tc(const float* __restrict__ bias) {
    extern __shared__ __align__(1024) char smem[];
    const uint32_t smem_base = (uint32_t)__cvta_generic_to_shared(smem);
    const int tid = threadIdx.x;
    const int wid = tid >> 5;
    const int l   = tid & 31;
    const int n0 = blockIdx.x * TILE_N;   // n fastest: A m-panel + B L2 reuse
    const int m0 = blockIdx.y * TILE_M;

    const int warp_m = wid & 3;           // 4 warps over M (64 rows each)
    const int warp_n = wid >> 2;          // 4 warps over N (32 cols each)

    // ldmatrix lane geometry:
    //   r=l&7 row-within-8, (l>>3)&1 -> +8 row, (l>>4)&1 -> +16B col
    const int r      = l & 7;
    const int rsel   = (l >> 3) & 1;
    const int csel   = (l >> 4) & 1;
    const uint32_t xorv = (uint32_t)r << 4;          // SW128 xor term
    uint32_t kcx[4];
#pragma unroll
    for (int ks = 0; ks < 4; ++ks)
        kcx[ks] = ((uint32_t)(ks * 32 + 16 * csel)) ^ xorv;

    const uint32_t aRow = (uint32_t)(warp_m * 64 + r + 8 * rsel) << 7;
    const uint32_t bRow = (uint32_t)(warp_n * 32 + r + 8 * rsel) << 7;

    float acc[4][4][4];
#pragma unroll
    for (int mt = 0; mt < 4; ++mt)
#pragma unroll
        for (int nt = 0; nt < 4; ++nt)
#pragma unroll
            for (int q = 0; q < 4; ++q) acc[mt][nt][q] = 0.f;

    fill_stage(0, 0, tid, smem_base, m0, n0);
    fill_stage(1, 1, tid, smem_base, m0, n0);
    fill_stage(2, 2, tid, smem_base, m0, n0);

    for (int kt = 0; kt < NKITER; ++kt) {
        const int s = kt & 3;
        if (kt < NKITER - 2) {
            asm volatile("cp.async.wait_group 2;" ::: "memory");
        } else if (kt == NKITER - 2) {
            asm volatile("cp.async.wait_group 1;" ::: "memory");
        } else {
            asm volatile("cp.async.wait_group 0;" ::: "memory");
        }
        __syncthreads();

        const uint32_t aBase = smem_base + SM_A_OFF(s) + aRow;
        const uint32_t bBase = smem_base + SM_B_OFF(s) + bRow;

#pragma unroll
        for (int ks = 0; ks < 4; ++ks) {
            uint32_t a[4][4], bf[2][4];
#pragma unroll
            for (int mt = 0; mt < 4; ++mt)
                ldsm_x4(a[mt], aBase + mt * 2048 + kcx[ks]);
#pragma unroll
            for (int ng = 0; ng < 2; ++ng)
                ldsm_x4(bf[ng], bBase + ng * 2048 + kcx[ks]);
#pragma unroll
            for (int mt = 0; mt < 4; ++mt) {
#pragma unroll
                for (int ng = 0; ng < 2; ++ng) {
                    mma16816(acc[mt][2 * ng],     a[mt], bf[ng][0], bf[ng][2]);
                    mma16816(acc[mt][2 * ng + 1], a[mt], bf[ng][1], bf[ng][3]);
                }
            }
        }

        if (kt + 3 < NKITER)
            fill_stage(kt + 3, (kt + 3) & 3, tid, smem_base, m0, n0);
    }

    // ---- epilogue: bias + activation -> g_gates ----
    const int region = n0 >> 10;                 // 0=z(tanh), 1/2=sigmoid
    const int mW = m0 + warp_m * 64;
    const int nW = n0 + warp_n * 32;
#pragma unroll
    for (int mt = 0; mt < 4; ++mt) {
#pragma unroll
        for (int nt = 0; nt < 4; ++nt) {
            const int col  = nW + nt * 8 + 2 * (l & 3);
            const float b0 = bias[col];
            const float b1 = bias[col + 1];
#pragma unroll
            for (int half = 0; half < 2; ++half) {
                const int row = mW + mt * 16 + (l >> 2) + 8 * half;
                float gx = acc[mt][nt][2 * half]     + b0;
                float gy = acc[mt][nt][2 * half + 1] + b1;
                float vx, vy;
                if (region == 0) {
                    vx = 2.f / (1.f + __expf(-2.f * gx)) - 1.f;
                    vy = 2.f / (1.f + __expf(-2.f * gy)) - 1.f;
                } else {
                    vx = 1.f / (1.f + __expf(-gx));
                    vy = 1.f / (1.f + __expf(-gy));
                }
                *(float2*)&g_gates[(size_t)row * NCH + col] = make_float2(vx, vy);
            }
        }
    }
}

// ---------------------------------------------------------------------------
// Chunked fo-pooling scan: c_t = f*(c_{t-1} - z) + z ;  h_t = o*c_t
// 16 chunks of 64 per (b,h) chain -> 262K threads.
// ---------------------------------------------------------------------------
__global__ __launch_bounds__(256)
void qrnn_scan_pass1() {
    const int idx   = blockIdx.x * 256 + threadIdx.x;   // 0..262143
    const int b     = idx >> 14;
    const int chunk = (idx >> 10) & 15;
    const int h     = idx & 1023;
    const float* __restrict__ g =
        g_gates + ((size_t)(b * TSEQ + chunk * 64)) * NCH + h;
    float c = 0.f, F = 1.f;
#pragma unroll 4
    for (int t = 0; t < 64; ++t) {
        const float z = g[(size_t)t * NCH];
        const float f = g[(size_t)t * NCH + HDIM];
        c = f * (c - z) + z;
        F *= f;
    }
    const size_t st = ((size_t)(b * 1024 + h) * 16 + chunk) * 2;
    g_state[st]     = F;
    g_state[st + 1] = c;
}

__global__ __launch_bounds__(256)
void qrnn_scan_combine() {
    const int chain = blockIdx.x * 256 + threadIdx.x;   // 0..16383
    const float* st = g_state + (size_t)chain * 32;
    float* ci = g_cin + (size_t)chain * 16;
    float c = 0.f;
#pragma unroll
    for (int ch = 0; ch < 16; ++ch) {
        ci[ch] = c;
        c = st[ch * 2] * c + st[ch * 2 + 1];
    }
}

__global__ __launch_bounds__(256)
void qrnn_scan_pass2(float* __restrict__ out) {
    const int idx   = blockIdx.x * 256 + threadIdx.x;
    const int b     = idx >> 14;
    const int chunk = (idx >> 10) & 15;
    const int h     = idx & 1023;
    const float* __restrict__ g =
        g_gates + ((size_t)(b * TSEQ + chunk * 64)) * NCH + h;
    float* __restrict__ cout = out + ((size_t)b * TSEQ + chunk * 64) * HDIM + h;
    float* __restrict__ hout = cout + (size_t)BBATCH * TSEQ * HDIM;

    float c = g_cin[(size_t)(b * 1024 + h) * 16 + chunk];
#pragma unroll 4
    for (int t = 0; t < 64; ++t) {
        const float z = __ldcs(&g[(size_t)t * NCH]);
        const float f = __ldcs(&g[(size_t)t * NCH + HDIM]);
        const float o = __ldcs(&g[(size_t)t * NCH + 2 * HDIM]);
        c = f * (c - z) + z;
        __stcs(&cout[(size_t)t * HDIM], c);          // final outputs: never re-read
        __stcs(&hout[(size_t)t * HDIM], o * c);
    }
}

// ---------------------------------------------------------------------------
extern "C" void kernel_launch(void* const* d_in, const int* in_sizes, int n_in,
                              void* d_out, int out_size)
{
    const float* x    = (const float*)d_in[0];   // [B, D, T]
    const float* w    = (const float*)d_in[1];   // [3H, D, 2]
    const float* bias = (const float*)d_in[2];   // [3H]
    float* out = (float*)d_out;

    cudaFuncSetAttribute(qrnn_gemm_tc, cudaFuncAttributeMaxDynamicSharedMemorySize,
                         GEMM_SMEM);

    prep_A_kernel<<<dim3(TSEQ / 32, DDIM / 32, BBATCH), dim3(32, 8)>>>(x);
    prep_B_kernel<<<(NCH * DDIM) / 512, 512>>>(w);

    qrnn_gemm_tc<<<dim3(NCH / TILE_N, MTOT / TILE_M), 512, GEMM_SMEM>>>(bias);

    qrnn_scan_pass1<<<(MTOT * 16) / 256, 256>>>();
    qrnn_scan_combine<<<MTOT / 256, 256>>>();
    qrnn_scan_pass2<<<(MTOT * 16) / 256, 256>>>(out);
}

// round 17
// speedup vs baseline: 7.9292x; 1.0087x over previous
#include <cuda_runtime.h>
#include <cuda_fp16.h>
#include <cstdint>
#include <math.h>

// ---------------------------------------------------------------------------
// Problem constants
// ---------------------------------------------------------------------------
#define BBATCH 16
#define DDIM   1024
#define TSEQ   1024
#define HDIM   1024
#define NCH    3072            // 3*H
#define MTOT   16384           // B*T
#define KTOT   2048            // logical K = 2 taps x 1024 channels (fp16 pass)
#define AROWS  1025            // physical A rows per batch: guard row + 1024

// GEMM tiling: CTA 256x128, 16 warps of 64x32, 4-stage cp.async
#define TILE_M 256
#define TILE_N 128
#define BKK    64
#define NKITER (KTOT / BKK)    // 32 k-tiles
#define NSTAGE 4

#define STAGE_BYTES  49152             // A 32KB + B 16KB
#define SM_A_OFF(s)  ((s) * STAGE_BYTES)
#define SM_B_OFF(s)  ((s) * STAGE_BYTES + 32768)
#define GEMM_SMEM    (NSTAGE * STAGE_BYTES)   // 196608

// ---------------------------------------------------------------------------
// Device scratch
// ---------------------------------------------------------------------------
// A_phys[b][r][d] = x[b,d,r-1] for r>=1; row 0 = zeros (causal guard).
// Logical A[m=(b,t)][tap*1024+d] = A_phys[b][t+tap][d].
__device__ __half g_A[(size_t)BBATCH * AROWS * DDIM];     //  33.6 MB
__device__ __half g_B[(size_t)NCH * KTOT];                //  12 MB
__device__ __half g_gates[(size_t)MTOT * NCH];            //  96 MB (activated z|f|o)
__device__ float  g_state[(size_t)MTOT * 16 * 2];         // per-chunk (F, r)
__device__ float  g_cin[(size_t)MTOT * 16];               // per-chunk c_in

// ---------------------------------------------------------------------------
// PTX helpers (plain sm_80-level: valid on sm_103 without 'a' features)
// ---------------------------------------------------------------------------
__device__ __forceinline__ void cp_async16(uint32_t dst, const void* src) {
    asm volatile("cp.async.cg.shared.global [%0], [%1], 16;" :: "r"(dst), "l"(src));
}
__device__ __forceinline__ void cp_commit() {
    asm volatile("cp.async.commit_group;" ::: "memory");
}

__device__ __forceinline__ void ldsm_x4(uint32_t* r, uint32_t addr) {
    asm volatile("ldmatrix.sync.aligned.m8n8.x4.shared.b16 {%0,%1,%2,%3}, [%4];"
                 : "=r"(r[0]), "=r"(r[1]), "=r"(r[2]), "=r"(r[3]) : "r"(addr));
}

__device__ __forceinline__ void mma16816(float* d, const uint32_t* a,
                                         uint32_t b0, uint32_t b1) {
    asm volatile(
        "mma.sync.aligned.m16n8k16.row.col.f32.f16.f16.f32 "
        "{%0,%1,%2,%3}, {%4,%5,%6,%7}, {%8,%9}, {%0,%1,%2,%3};"
        : "+f"(d[0]), "+f"(d[1]), "+f"(d[2]), "+f"(d[3])
        : "r"(a[0]), "r"(a[1]), "r"(a[2]), "r"(a[3]), "r"(b0), "r"(b1));
}

// ---------------------------------------------------------------------------
// prep_A: transpose x [B,D,T] -> A_phys fp16 [b][t+1][d], zero guard row 0.
// Single write per element (tap dedup happens via row-shift in the GEMM).
// ---------------------------------------------------------------------------
__global__ __launch_bounds__(256)
void prep_A_kernel(const float* __restrict__ x) {
    __shared__ float tile[32][33];
    const int b  = blockIdx.z;
    const int t0 = blockIdx.x * 32;
    const int d0 = blockIdx.y * 32;
    const int tx = threadIdx.x;      // 0..31
    const int ty = threadIdx.y;      // 0..7

#pragma unroll
    for (int i = 0; i < 4; ++i) {
        const int dl = ty + i * 8;
        tile[dl][tx] = x[((size_t)b * DDIM + d0 + dl) * TSEQ + t0 + tx];
    }
    __syncthreads();

#pragma unroll
    for (int i = 0; i < 4; ++i) {
        const int tl = ty + i * 8;
        const __half hv = __float2half_rn(tile[tx][tl]);
        const int t = t0 + tl;
        const int d = d0 + tx;
        g_A[((size_t)b * AROWS + t + 1) * DDIM + d] = hv;
        if (t == 0)                                  // causal guard row
            g_A[((size_t)b * AROWS) * DDIM + d] = __float2half_rn(0.f);
    }
}

// ---------------------------------------------------------------------------
// prep_B: w [3H, D, 2] -> B fp16 [n][k], k = tap*1024 + d
// ---------------------------------------------------------------------------
__global__ __launch_bounds__(512)
void prep_B_kernel(const float* __restrict__ w) {
    const int idx = blockIdx.x * 512 + threadIdx.x;   // over 3072*1024
    const int n = idx >> 10;
    const int d = idx & 1023;
    const float2 wv = *(const float2*)&w[(size_t)idx * 2];   // w[n][d][0..1]
    g_B[(size_t)n * KTOT + d]        = __float2half_rn(wv.x);
    g_B[(size_t)n * KTOT + 1024 + d] = __float2half_rn(wv.y);
}

// ---------------------------------------------------------------------------
// GEMM: g_gates = act( A @ B^T + bias ), K = 2048, single fp16 pass.
// CTA 256x128, 512 threads (16 warps, 64x32 warp tiles), BK=64, 4-stage
// cp.async pipeline, fp16 mma.sync (fp32 accumulate).
// A tiles come from A_phys with row base t0 + tap (tap = kt>>4):
//   kt 0..15  -> tap0 (x[t-1]) , d-offset (kt&15)*64
//   kt 16..31 -> tap1 (x[t])   , d-offset (kt&15)*64
// smem tiles: K-major 128B rows with SW128 xor swizzle (ldmatrix-friendly).
// ---------------------------------------------------------------------------
__device__ __forceinline__ void fill_stage(int kt, int s, int tid,
                                           uint32_t smem_base, int m0, int n0) {
    const int tap  = kt >> 4;
    const int doff = (kt & 15) * 64;
    const int b    = m0 >> 10;
    const int t0   = m0 & 1023;
    const char* Abase = (const char*)(g_A + ((size_t)b * AROWS + t0 + tap) * DDIM + doff);
    const char* Bbase = (const char*)(g_B + (size_t)n0 * KTOT + kt * 64);
#pragma unroll
    for (int i = 0; i < 4; ++i) {                    // A: 2048 x 16B
        const int c   = tid + i * 512;
        const int row = c >> 3;
        const int cb  = (c & 7) << 4;
        const uint32_t off = (row << 7) + cb;
        const uint32_t sw  = off ^ ((off >> 3) & 0x70);
        cp_async16(smem_base + SM_A_OFF(s) + sw,
                   Abase + (size_t)row * (DDIM * 2) + cb);
    }
#pragma unroll
    for (int i = 0; i < 2; ++i) {                    // B: 1024 x 16B
        const int c   = tid + i * 512;
        const int row = c >> 3;
        const int cb  = (c & 7) << 4;
        const uint32_t off = (row << 7) + cb;
        const uint32_t sw  = off ^ ((off >> 3) & 0x70);
        cp_async16(smem_base + SM_B_OFF(s) + sw,
                   Bbase + (size_t)row * (KTOT * 2) + cb);
    }
    cp_commit();
}

__global__ __launch_bounds__(512, 1)
void qrnn_gemm_tc(const float* __restrict__ bias) {
    extern __shared__ __align__(1024) char smem[];
    const uint32_t smem_base = (uint32_t)__cvta_generic_to_shared(smem);
    const int tid = threadIdx.x;
    const int wid = tid >> 5;
    const int l   = tid & 31;
    const int n0 = blockIdx.x * TILE_N;   // n fastest: A m-panel + B L2 reuse
    const int m0 = blockIdx.y * TILE_M;

    const int warp_m = wid & 3;           // 4 warps over M (64 rows each)
    const int warp_n = wid >> 2;          // 4 warps over N (32 cols each)

    // ldmatrix lane geometry:
    //   r=l&7 row-within-8, (l>>3)&1 -> +8 row, (l>>4)&1 -> +16B col
    const int r      = l & 7;
    const int rsel   = (l >> 3) & 1;
    const int csel   = (l >> 4) & 1;
    const uint32_t xorv = (uint32_t)r << 4;          // SW128 xor term
    uint32_t kcx[4];
#pragma unroll
    for (int ks = 0; ks < 4; ++ks)
        kcx[ks] = ((uint32_t)(ks * 32 + 16 * csel)) ^ xorv;

    const uint32_t aRow = (uint32_t)(warp_m * 64 + r + 8 * rsel) << 7;
    const uint32_t bRow = (uint32_t)(warp_n * 32 + r + 8 * rsel) << 7;

    float acc[4][4][4];
#pragma unroll
    for (int mt = 0; mt < 4; ++mt)
#pragma unroll
        for (int nt = 0; nt < 4; ++nt)
#pragma unroll
            for (int q = 0; q < 4; ++q) acc[mt][nt][q] = 0.f;

    fill_stage(0, 0, tid, smem_base, m0, n0);
    fill_stage(1, 1, tid, smem_base, m0, n0);
    fill_stage(2, 2, tid, smem_base, m0, n0);

    for (int kt = 0; kt < NKITER; ++kt) {
        const int s = kt & 3;
        if (kt < NKITER - 2) {
            asm volatile("cp.async.wait_group 2;" ::: "memory");
        } else if (kt == NKITER - 2) {
            asm volatile("cp.async.wait_group 1;" ::: "memory");
        } else {
            asm volatile("cp.async.wait_group 0;" ::: "memory");
        }
        __syncthreads();

        const uint32_t aBase = smem_base + SM_A_OFF(s) + aRow;
        const uint32_t bBase = smem_base + SM_B_OFF(s) + bRow;

#pragma unroll
        for (int ks = 0; ks < 4; ++ks) {
            uint32_t a[4][4], bf[2][4];
#pragma unroll
            for (int mt = 0; mt < 4; ++mt)
                ldsm_x4(a[mt], aBase + mt * 2048 + kcx[ks]);
#pragma unroll
            for (int ng = 0; ng < 2; ++ng)
                ldsm_x4(bf[ng], bBase + ng * 2048 + kcx[ks]);
#pragma unroll
            for (int mt = 0; mt < 4; ++mt) {
#pragma unroll
                for (int ng = 0; ng < 2; ++ng) {
                    mma16816(acc[mt][2 * ng],     a[mt], bf[ng][0], bf[ng][2]);
                    mma16816(acc[mt][2 * ng + 1], a[mt], bf[ng][1], bf[ng][3]);
                }
            }
        }

        if (kt + 3 < NKITER)
            fill_stage(kt + 3, (kt + 3) & 3, tid, smem_base, m0, n0);
    }

    // ---- epilogue: bias + activation -> g_gates (fp16, half2 stores) ----
    const int region = n0 >> 10;                 // 0=z(tanh), 1/2=sigmoid
    const int mW = m0 + warp_m * 64;
    const int nW = n0 + warp_n * 32;
#pragma unroll
    for (int mt = 0; mt < 4; ++mt) {
#pragma unroll
        for (int nt = 0; nt < 4; ++nt) {
            const int col  = nW + nt * 8 + 2 * (l & 3);
            const float b0 = bias[col];
            const float b1 = bias[col + 1];
#pragma unroll
            for (int half_ = 0; half_ < 2; ++half_) {
                const int row = mW + mt * 16 + (l >> 2) + 8 * half_;
                float gx = acc[mt][nt][2 * half_]     + b0;
                float gy = acc[mt][nt][2 * half_ + 1] + b1;
                float vx, vy;
                if (region == 0) {
                    vx = 2.f / (1.f + __expf(-2.f * gx)) - 1.f;
                    vy = 2.f / (1.f + __expf(-2.f * gy)) - 1.f;
                } else {
                    vx = 1.f / (1.f + __expf(-gx));
                    vy = 1.f / (1.f + __expf(-gy));
                }
                *(__half2*)&g_gates[(size_t)row * NCH + col] = __floats2half2_rn(vx, vy);
            }
        }
    }
}

// ---------------------------------------------------------------------------
// Chunked fo-pooling scan: c_t = f*(c_{t-1} - z) + z ;  h_t = o*c_t
// 16 chunks of 64 per (b,h) chain -> 262K threads. Gates are fp16.
// ---------------------------------------------------------------------------
__global__ __launch_bounds__(256)
void qrnn_scan_pass1() {
    const int idx   = blockIdx.x * 256 + threadIdx.x;   // 0..262143
    const int b     = idx >> 14;
    const int chunk = (idx >> 10) & 15;
    const int h     = idx & 1023;
    const __half* __restrict__ g =
        g_gates + ((size_t)(b * TSEQ + chunk * 64)) * NCH + h;
    float c = 0.f, F = 1.f;
#pragma unroll 4
    for (int t = 0; t < 64; ++t) {
        const float z = __half2float(g[(size_t)t * NCH]);
        const float f = __half2float(g[(size_t)t * NCH + HDIM]);
        c = f * (c - z) + z;
        F *= f;
    }
    const size_t st = ((size_t)(b * 1024 + h) * 16 + chunk) * 2;
    g_state[st]     = F;
    g_state[st + 1] = c;
}

__global__ __launch_bounds__(256)
void qrnn_scan_combine() {
    const int chain = blockIdx.x * 256 + threadIdx.x;   // 0..16383
    const float* st = g_state + (size_t)chain * 32;
    float* ci = g_cin + (size_t)chain * 16;
    float c = 0.f;
#pragma unroll
    for (int ch = 0; ch < 16; ++ch) {
        ci[ch] = c;
        c = st[ch * 2] * c + st[ch * 2 + 1];
    }
}

__global__ __launch_bounds__(256)
void qrnn_scan_pass2(float* __restrict__ out) {
    const int idx   = blockIdx.x * 256 + threadIdx.x;
    const int b     = idx >> 14;
    const int chunk = (idx >> 10) & 15;
    const int h     = idx & 1023;
    const __half* __restrict__ g =
        g_gates + ((size_t)(b * TSEQ + chunk * 64)) * NCH + h;
    float* __restrict__ cout = out + ((size_t)b * TSEQ + chunk * 64) * HDIM + h;
    float* __restrict__ hout = cout + (size_t)BBATCH * TSEQ * HDIM;

    float c = g_cin[(size_t)(b * 1024 + h) * 16 + chunk];
#pragma unroll 4
    for (int t = 0; t < 64; ++t) {
        const float z = __half2float(g[(size_t)t * NCH]);
        const float f = __half2float(g[(size_t)t * NCH + HDIM]);
        const float o = __half2float(g[(size_t)t * NCH + 2 * HDIM]);
        c = f * (c - z) + z;
        __stcs(&cout[(size_t)t * HDIM], c);          // final outputs: never re-read
        __stcs(&hout[(size_t)t * HDIM], o * c);
    }
}

// ---------------------------------------------------------------------------
extern "C" void kernel_launch(void* const* d_in, const int* in_sizes, int n_in,
                              void* d_out, int out_size)
{
    const float* x    = (const float*)d_in[0];   // [B, D, T]
    const float* w    = (const float*)d_in[1];   // [3H, D, 2]
    const float* bias = (const float*)d_in[2];   // [3H]
    float* out = (float*)d_out;

    cudaFuncSetAttribute(qrnn_gemm_tc, cudaFuncAttributeMaxDynamicSharedMemorySize,
                         GEMM_SMEM);

    prep_A_kernel<<<dim3(TSEQ / 32, DDIM / 32, BBATCH), dim3(32, 8)>>>(x);
    prep_B_kernel<<<(NCH * DDIM) / 512, 512>>>(w);

    qrnn_gemm_tc<<<dim3(NCH / TILE_N, MTOT / TILE_M), 512, GEMM_SMEM>>>(bias);

    qrnn_scan_pass1<<<(MTOT * 16) / 256, 256>>>();
    qrnn_scan_combine<<<MTOT / 256, 256>>>();
    qrnn_scan_pass2<<<(MTOT * 16) / 256, 256>>>(out);
}